// round 11
// baseline (speedup 1.0000x reference)
#include <cuda_runtime.h>
#include <cuda_fp16.h>

// MedianBlur 5x5, fp32 I/O, 12 images of 1024x1024, zero padding (same).
// Round-11: shared vertical sort4 ("quad") staging. Windows at out-rows
// (2i, 2i+1) share rows 2i+1..2i+4: one cooperative sort4 per (row-pair,
// packed col) stored in smem; each window rebuilds its exact sorted-5
// column with one 8-op rank-insert. Same sorted multisets -> bit-identical
// outputs. Network = round 9/10 (11-candidate pruned selection).

#define IMG_H 1024
#define IMG_W 1024
#define NIMG  12

#define TILE_W 128            // output cols per block (32 threads * 4 px)
#define OUT_H  16             // output rows per block (8 row-pairs)
#define SMEM_H 20             // OUT_H + 4 halo
#define KCOLS 34              // packed cols per group: c = 4*k + g, c in [0,136)
#define NQUAD 8               // row-pairs per block

typedef __half2 h2;

__device__ __forceinline__ h2 mn2(h2 a, h2 b) { return __hmin2(a, b); }
__device__ __forceinline__ h2 mx2(h2 a, h2 b) { return __hmax2(a, b); }

__device__ __forceinline__ void ce(h2& a, h2& b) {
    h2 t = mn2(a, b);
    b = mx2(a, b);
    a = t;
}

// Constrained merge of top chains, DROPPING rank 0 (provably non-median). 5 ops.
__device__ __forceinline__ void merge_top4(h2 x0, h2 x1, h2 y0, h2 y1, h2 y2,
                                           h2& a1, h2& a2, h2& a3, h2& a4) {
    h2 p = mx2(x0, y0);
    h2 q = mn2(x1, y1);
    a3 = mx2(x1, y1);
    a1 = mn2(p, q);
    a2 = mx2(p, q);
    a4 = y2;
}

// Constrained merge of bottom chains, DROPPING rank 4 (provably non-median). 5 ops.
__device__ __forceinline__ void merge_bot4(h2 x0, h2 x1, h2 y0, h2 y1, h2 y2,
                                           h2& b0, h2& b1, h2& b2, h2& b3) {
    b0 = y0;
    b1 = mn2(x0, y1);
    h2 p = mx2(x0, y1);
    h2 q = mn2(x1, y2);
    b2 = mn2(p, q);
    b3 = mx2(p, q);
}

// Batcher odd-even merge of two sorted 4-chains, ONLY ranks 2..5 of 8. 14 ops.
__device__ __forceinline__ void merge44_mid4(h2 a1, h2 a2, h2 a3, h2 a4,
                                             h2 b0, h2 b1, h2 b2, h2 b3,
                                             h2& s0, h2& s1, h2& s2, h2& s3) {
    h2 t  = mx2(a1, b0);
    h2 u  = mn2(a3, b2);
    h2 E3 = mx2(a3, b2);
    h2 E1 = mn2(t, u);
    h2 E2 = mx2(t, u);
    h2 O0 = mn2(a2, b1);
    h2 t2 = mx2(a2, b1);
    h2 u2 = mn2(a4, b3);
    h2 O1 = mn2(t2, u2);
    h2 O2 = mx2(t2, u2);
    s0 = mx2(O0, E1);
    s1 = mn2(O1, E2);
    s2 = mx2(O1, E2);
    s3 = mn2(O2, E3);
}

// Finisher: med11 == med7({s0<=s1<=s2<=s3} U {m0<=m1<=m2}). 10 ops.
__device__ __forceinline__ h2 med7_fin(h2 s0, h2 s1, h2 s2, h2 s3,
                                       h2 m0, h2 m1, h2 m2) {
    h2 u0 = mx2(s0, m0);
    h2 u3 = mn2(s3, m2);
    h2 p = mn2(u3, m1);
    h2 q = mx2(u3, m1);
    h2 a = mx2(s1, p);
    h2 b = mn2(s2, q);
    h2 lo = mn2(a, b);
    h2 hi = mx2(a, b);
    return mx2(lo, mn2(hi, u0));
}

__global__ __launch_bounds__(256, 6)
void median5x5_h2_kernel(const float* __restrict__ in, float* __restrict__ out) {
    // Raw packed tile: P2[c] = (h[c], h[c+2]), c = 4k+g, p2t[r][k][g],
    // g contiguous (16B) for wide LDS/STS.
    __shared__ __align__(16) h2 p2t[SMEM_H][KCOLS][4];
    // Quads: qd[i][c][0..3] = ascending sort4 of P2[c] over smem rows 2i+1..2i+4.
    __shared__ __align__(16) h2 qd[NQUAD][KCOLS * 4][4];

    const int n   = blockIdx.z;
    const int x0b = blockIdx.x * TILE_W;
    const int y0b = blockIdx.y * OUT_H;
    const float* img = in + (size_t)n * IMG_H * IMG_W;

    const int tx = threadIdx.x;
    const int ty = threadIdx.y;
    const int tid = ty * 32 + tx;

    // ---- Phase 1: raw packed tile (fp32 -> packed fp16 pairs), zero pad ----
    for (int i = tid; i < SMEM_H * KCOLS; i += 256) {
        const int r  = i / KCOLS;
        const int k  = i - r * KCOLS;
        const int gy  = y0b + r - 2;
        const int gx0 = x0b - 4 + k * 4;
        float f0 = 0.f, f1 = 0.f, f2 = 0.f, f3 = 0.f, f4 = 0.f, f5 = 0.f;
        if ((unsigned)gy < IMG_H) {
            const float* rowp = img + (size_t)gy * IMG_W;
            if (gx0 >= 0 && gx0 + 5 < IMG_W) {
                const float4 fa = *reinterpret_cast<const float4*>(rowp + gx0);
                const float2 fb = *reinterpret_cast<const float2*>(rowp + gx0 + 4);
                f0 = fa.x; f1 = fa.y; f2 = fa.z; f3 = fa.w; f4 = fb.x; f5 = fb.y;
            } else {
                if ((unsigned)gx0       < IMG_W) f0 = rowp[gx0];
                if ((unsigned)(gx0 + 1) < IMG_W) f1 = rowp[gx0 + 1];
                if ((unsigned)(gx0 + 2) < IMG_W) f2 = rowp[gx0 + 2];
                if ((unsigned)(gx0 + 3) < IMG_W) f3 = rowp[gx0 + 3];
                if ((unsigned)(gx0 + 4) < IMG_W) f4 = rowp[gx0 + 4];
                if ((unsigned)(gx0 + 5) < IMG_W) f5 = rowp[gx0 + 5];
            }
        }
        const h2 p0 = __float22half2_rn(make_float2(f0, f2));
        const h2 p1 = __float22half2_rn(make_float2(f1, f3));
        const h2 p2 = __float22half2_rn(make_float2(f2, f4));
        const h2 p3 = __float22half2_rn(make_float2(f3, f5));
        uint4 w;
        w.x = *reinterpret_cast<const unsigned*>(&p0);
        w.y = *reinterpret_cast<const unsigned*>(&p1);
        w.z = *reinterpret_cast<const unsigned*>(&p2);
        w.w = *reinterpret_cast<const unsigned*>(&p3);
        *reinterpret_cast<uint4*>(&p2t[r][k][0]) = w;
    }
    __syncthreads();

    // ---- Phase 2: cooperative quads. Task (i,k): sort rows 2i+1..2i+4 for
    // the 4 packed cols 4k+g, elementwise h2. ----
    for (int t = tid; t < NQUAD * KCOLS; t += 256) {
        const int i = t / KCOLS;
        const int k = t - i * KCOLS;
        const int rb = 2 * i + 1;
        const uint4 w1 = *reinterpret_cast<const uint4*>(&p2t[rb + 0][k][0]);
        const uint4 w2 = *reinterpret_cast<const uint4*>(&p2t[rb + 1][k][0]);
        const uint4 w3 = *reinterpret_cast<const uint4*>(&p2t[rb + 2][k][0]);
        const uint4 w4 = *reinterpret_cast<const uint4*>(&p2t[rb + 3][k][0]);
        const unsigned* u1 = reinterpret_cast<const unsigned*>(&w1);
        const unsigned* u2 = reinterpret_cast<const unsigned*>(&w2);
        const unsigned* u3 = reinterpret_cast<const unsigned*>(&w3);
        const unsigned* u4 = reinterpret_cast<const unsigned*>(&w4);
        #pragma unroll
        for (int g = 0; g < 4; g++) {
            h2 a = *reinterpret_cast<const h2*>(&u1[g]);
            h2 b = *reinterpret_cast<const h2*>(&u2[g]);
            h2 c = *reinterpret_cast<const h2*>(&u3[g]);
            h2 d = *reinterpret_cast<const h2*>(&u4[g]);
            ce(a, b); ce(c, d); ce(a, c); ce(b, d); ce(b, c);
            uint4 w;
            w.x = *reinterpret_cast<const unsigned*>(&a);
            w.y = *reinterpret_cast<const unsigned*>(&b);
            w.z = *reinterpret_cast<const unsigned*>(&c);
            w.w = *reinterpret_cast<const unsigned*>(&d);
            *reinterpret_cast<uint4*>(&qd[i][k * 4 + g][0]) = w;
        }
    }
    __syncthreads();

    // ---- Phase 3: two windows per thread (out rows 2ty, 2ty+1) ----
    #pragma unroll 1
    for (int wi = 0; wi < 2; wi++) {
        const int o = 2 * ty + wi;                 // local window base row
        const int xr = (wi == 0) ? (2 * ty) : (2 * ty + 5);  // inserted raw row

        // Rebuild exact sorted-5 columns: quad (LDS.128) + rank-insert raw.
        h2 col[6][5];
        {
            const uint2 lo = *reinterpret_cast<const uint2*>(&p2t[xr][tx][2]);
            const uint4 hi = *reinterpret_cast<const uint4*>(&p2t[xr][tx + 1][0]);
            const unsigned raw[6] = {lo.x, lo.y, hi.x, hi.y, hi.z, hi.w};
            #pragma unroll
            for (int m = 0; m < 6; m++) {
                const uint4 qw = *reinterpret_cast<const uint4*>(&qd[ty][4 * tx + 2 + m][0]);
                const h2 q0 = *reinterpret_cast<const h2*>(&qw.x);
                const h2 q1 = *reinterpret_cast<const h2*>(&qw.y);
                const h2 q2 = *reinterpret_cast<const h2*>(&qw.z);
                const h2 q3 = *reinterpret_cast<const h2*>(&qw.w);
                const h2 x  = *reinterpret_cast<const h2*>(&raw[m]);
                col[m][0] = mn2(q0, x);
                col[m][1] = mx2(q0, mn2(q1, x));
                col[m][2] = mx2(q1, mn2(q2, x));
                col[m][3] = mx2(q2, mn2(q3, x));
                col[m][4] = mx2(q3, x);
            }
        }

        // ---- Row phase: partial shared sorts of cols 1..4, rank-insert c0/c5 ----
        h2 a03, a04, a12, a13, a14, aM1, aM2, aM3, a30, a31, a32, a40, a41;
        h2 b03, b04, b12, b13, b14, bM1, bM2, bM3, b30, b31, b32, b40, b41;

        {   // row 0: top2 of 4, insert -> ranks {3,4}
            h2 a = mn2(col[1][0], col[2][0]), b = mx2(col[1][0], col[2][0]);
            h2 c = mn2(col[3][0], col[4][0]), d = mx2(col[3][0], col[4][0]);
            h2 q3 = mx2(b, d);
            h2 q2 = mx2(mn2(b, d), mx2(a, c));
            h2 xa = col[0][0], xb = col[5][0];
            a04 = mx2(q3, xa); a03 = mx2(q2, mn2(q3, xa));
            b04 = mx2(q3, xb); b03 = mx2(q2, mn2(q3, xb));
        }
        {   // row 1: sort4 minus q0, insert -> ranks {2,3,4}
            h2 v0 = col[1][1], v1 = col[2][1], v2 = col[3][1], v3 = col[4][1];
            ce(v0, v1); ce(v2, v3);
            v2 = mx2(v0, v2);
            ce(v1, v3); ce(v1, v2);
            const h2 q1 = v1, q2 = v2, q3 = v3;
            h2 xa = col[0][1], xb = col[5][1];
            a14 = mx2(q3, xa); a13 = mx2(q2, mn2(q3, xa)); a12 = mx2(q1, mn2(q2, xa));
            b14 = mx2(q3, xb); b13 = mx2(q2, mn2(q3, xb)); b12 = mx2(q1, mn2(q2, xb));
        }
        {   // row 2: full sort4, insert -> mid3 ranks {1,2,3}
            h2 q0 = col[1][2], q1 = col[2][2], q2 = col[3][2], q3 = col[4][2];
            ce(q0, q1); ce(q2, q3); ce(q0, q2); ce(q1, q3); ce(q1, q2);
            h2 xa = col[0][2], xb = col[5][2];
            aM3 = mx2(q2, mn2(q3, xa)); aM2 = mx2(q1, mn2(q2, xa)); aM1 = mx2(q0, mn2(q1, xa));
            bM3 = mx2(q2, mn2(q3, xb)); bM2 = mx2(q1, mn2(q2, xb)); bM1 = mx2(q0, mn2(q1, xb));
        }
        {   // row 3: sort4 minus q3, insert -> ranks {0,1,2}
            h2 v0 = col[1][3], v1 = col[2][3], v2 = col[3][3], v3 = col[4][3];
            ce(v0, v1); ce(v2, v3); ce(v0, v2);
            v1 = mn2(v1, v3);
            ce(v1, v2);
            const h2 q0 = v0, q1 = v1, q2 = v2;
            h2 xa = col[0][3], xb = col[5][3];
            a30 = mn2(q0, xa); a31 = mx2(q0, mn2(q1, xa)); a32 = mx2(q1, mn2(q2, xa));
            b30 = mn2(q0, xb); b31 = mx2(q0, mn2(q1, xb)); b32 = mx2(q1, mn2(q2, xb));
        }
        {   // row 4: bottom2 of 4, insert -> ranks {0,1}
            h2 a = mn2(col[1][4], col[2][4]), b = mx2(col[1][4], col[2][4]);
            h2 c = mn2(col[3][4], col[4][4]), d = mx2(col[3][4], col[4][4]);
            h2 q0 = mn2(a, c);
            h2 q1 = mn2(mx2(a, c), mn2(b, d));
            h2 xa = col[0][4], xb = col[5][4];
            a40 = mn2(q0, xa); a41 = mx2(q0, mn2(q1, xa));
            b40 = mn2(q0, xb); b41 = mx2(q0, mn2(q1, xb));
        }

        // ---- Merge phase per network (pruned 11-candidate selection) ----
        h2 rA, rB;
        {
            h2 a1, a2, a3, a4, c0, c1, c2, c3;
            merge_top4(a03, a04, a12, a13, a14, a1, a2, a3, a4);
            merge_bot4(a40, a41, a30, a31, a32, c0, c1, c2, c3);
            h2 s0, s1, s2, s3;
            merge44_mid4(a1, a2, a3, a4, c0, c1, c2, c3, s0, s1, s2, s3);
            rA = med7_fin(s0, s1, s2, s3, aM1, aM2, aM3);
        }
        {
            h2 a1, a2, a3, a4, c0, c1, c2, c3;
            merge_top4(b03, b04, b12, b13, b14, a1, a2, a3, a4);
            merge_bot4(b40, b41, b30, b31, b32, c0, c1, c2, c3);
            h2 s0, s1, s2, s3;
            merge44_mid4(a1, a2, a3, a4, c0, c1, c2, c3, s0, s1, s2, s3);
            rB = med7_fin(s0, s1, s2, s3, bM1, bM2, bM3);
        }

        float4 res;
        res.x = __low2float(rA);    // pixel p0
        res.y = __low2float(rB);    // pixel p0+1
        res.z = __high2float(rA);   // pixel p0+2
        res.w = __high2float(rB);   // pixel p0+3

        float* orow = out + (size_t)n * IMG_H * IMG_W
                          + (size_t)(y0b + o) * IMG_W + x0b + tx * 4;
        *reinterpret_cast<float4*>(orow) = res;
    }
}

extern "C" void kernel_launch(void* const* d_in, const int* in_sizes, int n_in,
                              void* d_out, int out_size) {
    (void)in_sizes; (void)n_in; (void)out_size;
    const float* in = (const float*)d_in[0];
    float* out = (float*)d_out;

    dim3 block(32, 8, 1);
    dim3 grid(IMG_W / TILE_W, IMG_H / OUT_H, NIMG);
    median5x5_h2_kernel<<<grid, block>>>(in, out);
}

// round 12
// speedup vs baseline: 1.2525x; 1.2525x over previous
#include <cuda_runtime.h>
#include <cuda_fp16.h>

// MedianBlur 5x5, fp32 I/O, 12 images of 1024x1024, zero padding (same).
// Round-12: round-11 quad sharing with a CONFLICT-FREE quad layout.
// qd[i][g][k][4] group-interleaved (like p2t) so consumer quad loads have
// 16B lane stride -> no LDS bank conflicts (round-11's qd[i][c][4] had a
// 64B stride -> 4-way conflicts -> L1 75.9%). Windows at out-rows (2i,2i+1)
// share one sort4 of rows 2i+1..2i+4 per packed column; each window
// rebuilds its exact sorted-5 column with one 8-op rank-insert.
// Network = rounds 9-11 (11-candidate pruned selection).

#define IMG_H 1024
#define IMG_W 1024
#define NIMG  12

#define TILE_W 128            // output cols per block (32 threads * 4 px)
#define OUT_H  16             // output rows per block (8 row-pairs)
#define SMEM_H 20             // OUT_H + 4 halo
#define KCOLS 34              // packed cols per group: c = 4*k + g, c in [0,136)
#define NQUAD 8               // row-pairs per block

typedef __half2 h2;

__device__ __forceinline__ h2 mn2(h2 a, h2 b) { return __hmin2(a, b); }
__device__ __forceinline__ h2 mx2(h2 a, h2 b) { return __hmax2(a, b); }

__device__ __forceinline__ void ce(h2& a, h2& b) {
    h2 t = mn2(a, b);
    b = mx2(a, b);
    a = t;
}

// Constrained merge of top chains, DROPPING rank 0 (provably non-median). 5 ops.
__device__ __forceinline__ void merge_top4(h2 x0, h2 x1, h2 y0, h2 y1, h2 y2,
                                           h2& a1, h2& a2, h2& a3, h2& a4) {
    h2 p = mx2(x0, y0);
    h2 q = mn2(x1, y1);
    a3 = mx2(x1, y1);
    a1 = mn2(p, q);
    a2 = mx2(p, q);
    a4 = y2;
}

// Constrained merge of bottom chains, DROPPING rank 4 (provably non-median). 5 ops.
__device__ __forceinline__ void merge_bot4(h2 x0, h2 x1, h2 y0, h2 y1, h2 y2,
                                           h2& b0, h2& b1, h2& b2, h2& b3) {
    b0 = y0;
    b1 = mn2(x0, y1);
    h2 p = mx2(x0, y1);
    h2 q = mn2(x1, y2);
    b2 = mn2(p, q);
    b3 = mx2(p, q);
}

// Batcher odd-even merge of two sorted 4-chains, ONLY ranks 2..5 of 8. 14 ops.
__device__ __forceinline__ void merge44_mid4(h2 a1, h2 a2, h2 a3, h2 a4,
                                             h2 b0, h2 b1, h2 b2, h2 b3,
                                             h2& s0, h2& s1, h2& s2, h2& s3) {
    h2 t  = mx2(a1, b0);
    h2 u  = mn2(a3, b2);
    h2 E3 = mx2(a3, b2);
    h2 E1 = mn2(t, u);
    h2 E2 = mx2(t, u);
    h2 O0 = mn2(a2, b1);
    h2 t2 = mx2(a2, b1);
    h2 u2 = mn2(a4, b3);
    h2 O1 = mn2(t2, u2);
    h2 O2 = mx2(t2, u2);
    s0 = mx2(O0, E1);
    s1 = mn2(O1, E2);
    s2 = mx2(O1, E2);
    s3 = mn2(O2, E3);
}

// Finisher: med11 == med7({s0<=s1<=s2<=s3} U {m0<=m1<=m2}). 10 ops.
__device__ __forceinline__ h2 med7_fin(h2 s0, h2 s1, h2 s2, h2 s3,
                                       h2 m0, h2 m1, h2 m2) {
    h2 u0 = mx2(s0, m0);
    h2 u3 = mn2(s3, m2);
    h2 p = mn2(u3, m1);
    h2 q = mx2(u3, m1);
    h2 a = mx2(s1, p);
    h2 b = mn2(s2, q);
    h2 lo = mn2(a, b);
    h2 hi = mx2(a, b);
    return mx2(lo, mn2(hi, u0));
}

__global__ __launch_bounds__(256, 6)
void median5x5_h2_kernel(const float* __restrict__ in, float* __restrict__ out) {
    // Raw packed tile: P2[c] = (h[c], h[c+2]), c = 4k+g, p2t[r][k][g],
    // g contiguous (16B) for wide LDS/STS, 16B lane stride in k.
    __shared__ __align__(16) h2 p2t[SMEM_H][KCOLS][4];
    // Quads, group-interleaved: qd[i][g][k][0..3] = ascending sort4 of
    // packed col c = 4k+g over smem rows 2i+1..2i+4. Consumer loads
    // qd[ty][(2+m)&3][tx+((2+m)>>2)] -> 16B lane stride, conflict-free.
    __shared__ __align__(16) h2 qd[NQUAD][4][KCOLS][4];

    const int n   = blockIdx.z;
    const int x0b = blockIdx.x * TILE_W;
    const int y0b = blockIdx.y * OUT_H;
    const float* img = in + (size_t)n * IMG_H * IMG_W;

    const int tx = threadIdx.x;
    const int ty = threadIdx.y;
    const int tid = ty * 32 + tx;

    // ---- Phase 1: raw packed tile (fp32 -> packed fp16 pairs), zero pad ----
    for (int i = tid; i < SMEM_H * KCOLS; i += 256) {
        const int r  = i / KCOLS;
        const int k  = i - r * KCOLS;
        const int gy  = y0b + r - 2;
        const int gx0 = x0b - 4 + k * 4;
        float f0 = 0.f, f1 = 0.f, f2 = 0.f, f3 = 0.f, f4 = 0.f, f5 = 0.f;
        if ((unsigned)gy < IMG_H) {
            const float* rowp = img + (size_t)gy * IMG_W;
            if (gx0 >= 0 && gx0 + 5 < IMG_W) {
                const float4 fa = *reinterpret_cast<const float4*>(rowp + gx0);
                const float2 fb = *reinterpret_cast<const float2*>(rowp + gx0 + 4);
                f0 = fa.x; f1 = fa.y; f2 = fa.z; f3 = fa.w; f4 = fb.x; f5 = fb.y;
            } else {
                if ((unsigned)gx0       < IMG_W) f0 = rowp[gx0];
                if ((unsigned)(gx0 + 1) < IMG_W) f1 = rowp[gx0 + 1];
                if ((unsigned)(gx0 + 2) < IMG_W) f2 = rowp[gx0 + 2];
                if ((unsigned)(gx0 + 3) < IMG_W) f3 = rowp[gx0 + 3];
                if ((unsigned)(gx0 + 4) < IMG_W) f4 = rowp[gx0 + 4];
                if ((unsigned)(gx0 + 5) < IMG_W) f5 = rowp[gx0 + 5];
            }
        }
        const h2 p0 = __float22half2_rn(make_float2(f0, f2));
        const h2 p1 = __float22half2_rn(make_float2(f1, f3));
        const h2 p2 = __float22half2_rn(make_float2(f2, f4));
        const h2 p3 = __float22half2_rn(make_float2(f3, f5));
        uint4 w;
        w.x = *reinterpret_cast<const unsigned*>(&p0);
        w.y = *reinterpret_cast<const unsigned*>(&p1);
        w.z = *reinterpret_cast<const unsigned*>(&p2);
        w.w = *reinterpret_cast<const unsigned*>(&p3);
        *reinterpret_cast<uint4*>(&p2t[r][k][0]) = w;
    }
    __syncthreads();

    // ---- Phase 2: cooperative quads. Task (i,k): sort rows 2i+1..2i+4 of
    // packed cols 4k+g (g=0..3), elementwise h2; store group-interleaved. ----
    for (int t = tid; t < NQUAD * KCOLS; t += 256) {
        const int i = t / KCOLS;
        const int k = t - i * KCOLS;
        const int rb = 2 * i + 1;
        const uint4 w1 = *reinterpret_cast<const uint4*>(&p2t[rb + 0][k][0]);
        const uint4 w2 = *reinterpret_cast<const uint4*>(&p2t[rb + 1][k][0]);
        const uint4 w3 = *reinterpret_cast<const uint4*>(&p2t[rb + 2][k][0]);
        const uint4 w4 = *reinterpret_cast<const uint4*>(&p2t[rb + 3][k][0]);
        const unsigned* u1 = reinterpret_cast<const unsigned*>(&w1);
        const unsigned* u2 = reinterpret_cast<const unsigned*>(&w2);
        const unsigned* u3 = reinterpret_cast<const unsigned*>(&w3);
        const unsigned* u4 = reinterpret_cast<const unsigned*>(&w4);
        #pragma unroll
        for (int g = 0; g < 4; g++) {
            h2 a = *reinterpret_cast<const h2*>(&u1[g]);
            h2 b = *reinterpret_cast<const h2*>(&u2[g]);
            h2 c = *reinterpret_cast<const h2*>(&u3[g]);
            h2 d = *reinterpret_cast<const h2*>(&u4[g]);
            ce(a, b); ce(c, d); ce(a, c); ce(b, d); ce(b, c);
            uint4 w;
            w.x = *reinterpret_cast<const unsigned*>(&a);
            w.y = *reinterpret_cast<const unsigned*>(&b);
            w.z = *reinterpret_cast<const unsigned*>(&c);
            w.w = *reinterpret_cast<const unsigned*>(&d);
            *reinterpret_cast<uint4*>(&qd[i][g][k][0]) = w;
        }
    }
    __syncthreads();

    // ---- Phase 3: two windows per thread (out rows 2ty, 2ty+1) ----
    #pragma unroll 1
    for (int wi = 0; wi < 2; wi++) {
        const int o = 2 * ty + wi;                 // local window base row
        const int xr = (wi == 0) ? (2 * ty) : (2 * ty + 5);  // inserted raw row

        // Rebuild exact sorted-5 columns: quad (LDS.128) + rank-insert raw.
        h2 col[6][5];
        {
            const uint2 lo = *reinterpret_cast<const uint2*>(&p2t[xr][tx][2]);
            const uint4 hi = *reinterpret_cast<const uint4*>(&p2t[xr][tx + 1][0]);
            const unsigned raw[6] = {lo.x, lo.y, hi.x, hi.y, hi.z, hi.w};
            #pragma unroll
            for (int m = 0; m < 6; m++) {
                const int g  = (2 + m) & 3;
                const int kk = tx + ((2 + m) >> 2);
                const uint4 qw = *reinterpret_cast<const uint4*>(&qd[ty][g][kk][0]);
                const h2 q0 = *reinterpret_cast<const h2*>(&qw.x);
                const h2 q1 = *reinterpret_cast<const h2*>(&qw.y);
                const h2 q2 = *reinterpret_cast<const h2*>(&qw.z);
                const h2 q3 = *reinterpret_cast<const h2*>(&qw.w);
                const h2 x  = *reinterpret_cast<const h2*>(&raw[m]);
                col[m][0] = mn2(q0, x);
                col[m][1] = mx2(q0, mn2(q1, x));
                col[m][2] = mx2(q1, mn2(q2, x));
                col[m][3] = mx2(q2, mn2(q3, x));
                col[m][4] = mx2(q3, x);
            }
        }

        // ---- Row phase: partial shared sorts of cols 1..4, rank-insert c0/c5 ----
        h2 a03, a04, a12, a13, a14, aM1, aM2, aM3, a30, a31, a32, a40, a41;
        h2 b03, b04, b12, b13, b14, bM1, bM2, bM3, b30, b31, b32, b40, b41;

        {   // row 0: top2 of 4, insert -> ranks {3,4}
            h2 a = mn2(col[1][0], col[2][0]), b = mx2(col[1][0], col[2][0]);
            h2 c = mn2(col[3][0], col[4][0]), d = mx2(col[3][0], col[4][0]);
            h2 q3 = mx2(b, d);
            h2 q2 = mx2(mn2(b, d), mx2(a, c));
            h2 xa = col[0][0], xb = col[5][0];
            a04 = mx2(q3, xa); a03 = mx2(q2, mn2(q3, xa));
            b04 = mx2(q3, xb); b03 = mx2(q2, mn2(q3, xb));
        }
        {   // row 1: sort4 minus q0, insert -> ranks {2,3,4}
            h2 v0 = col[1][1], v1 = col[2][1], v2 = col[3][1], v3 = col[4][1];
            ce(v0, v1); ce(v2, v3);
            v2 = mx2(v0, v2);
            ce(v1, v3); ce(v1, v2);
            const h2 q1 = v1, q2 = v2, q3 = v3;
            h2 xa = col[0][1], xb = col[5][1];
            a14 = mx2(q3, xa); a13 = mx2(q2, mn2(q3, xa)); a12 = mx2(q1, mn2(q2, xa));
            b14 = mx2(q3, xb); b13 = mx2(q2, mn2(q3, xb)); b12 = mx2(q1, mn2(q2, xb));
        }
        {   // row 2: full sort4, insert -> mid3 ranks {1,2,3}
            h2 q0 = col[1][2], q1 = col[2][2], q2 = col[3][2], q3 = col[4][2];
            ce(q0, q1); ce(q2, q3); ce(q0, q2); ce(q1, q3); ce(q1, q2);
            h2 xa = col[0][2], xb = col[5][2];
            aM3 = mx2(q2, mn2(q3, xa)); aM2 = mx2(q1, mn2(q2, xa)); aM1 = mx2(q0, mn2(q1, xa));
            bM3 = mx2(q2, mn2(q3, xb)); bM2 = mx2(q1, mn2(q2, xb)); bM1 = mx2(q0, mn2(q1, xb));
        }
        {   // row 3: sort4 minus q3, insert -> ranks {0,1,2}
            h2 v0 = col[1][3], v1 = col[2][3], v2 = col[3][3], v3 = col[4][3];
            ce(v0, v1); ce(v2, v3); ce(v0, v2);
            v1 = mn2(v1, v3);
            ce(v1, v2);
            const h2 q0 = v0, q1 = v1, q2 = v2;
            h2 xa = col[0][3], xb = col[5][3];
            a30 = mn2(q0, xa); a31 = mx2(q0, mn2(q1, xa)); a32 = mx2(q1, mn2(q2, xa));
            b30 = mn2(q0, xb); b31 = mx2(q0, mn2(q1, xb)); b32 = mx2(q1, mn2(q2, xb));
        }
        {   // row 4: bottom2 of 4, insert -> ranks {0,1}
            h2 a = mn2(col[1][4], col[2][4]), b = mx2(col[1][4], col[2][4]);
            h2 c = mn2(col[3][4], col[4][4]), d = mx2(col[3][4], col[4][4]);
            h2 q0 = mn2(a, c);
            h2 q1 = mn2(mx2(a, c), mn2(b, d));
            h2 xa = col[0][4], xb = col[5][4];
            a40 = mn2(q0, xa); a41 = mx2(q0, mn2(q1, xa));
            b40 = mn2(q0, xb); b41 = mx2(q0, mn2(q1, xb));
        }

        // ---- Merge phase per network (pruned 11-candidate selection) ----
        h2 rA, rB;
        {
            h2 a1, a2, a3, a4, c0, c1, c2, c3;
            merge_top4(a03, a04, a12, a13, a14, a1, a2, a3, a4);
            merge_bot4(a40, a41, a30, a31, a32, c0, c1, c2, c3);
            h2 s0, s1, s2, s3;
            merge44_mid4(a1, a2, a3, a4, c0, c1, c2, c3, s0, s1, s2, s3);
            rA = med7_fin(s0, s1, s2, s3, aM1, aM2, aM3);
        }
        {
            h2 a1, a2, a3, a4, c0, c1, c2, c3;
            merge_top4(b03, b04, b12, b13, b14, a1, a2, a3, a4);
            merge_bot4(b40, b41, b30, b31, b32, c0, c1, c2, c3);
            h2 s0, s1, s2, s3;
            merge44_mid4(a1, a2, a3, a4, c0, c1, c2, c3, s0, s1, s2, s3);
            rB = med7_fin(s0, s1, s2, s3, bM1, bM2, bM3);
        }

        float4 res;
        res.x = __low2float(rA);    // pixel p0
        res.y = __low2float(rB);    // pixel p0+1
        res.z = __high2float(rA);   // pixel p0+2
        res.w = __high2float(rB);   // pixel p0+3

        float* orow = out + (size_t)n * IMG_H * IMG_W
                          + (size_t)(y0b + o) * IMG_W + x0b + tx * 4;
        *reinterpret_cast<float4*>(orow) = res;
    }
}

extern "C" void kernel_launch(void* const* d_in, const int* in_sizes, int n_in,
                              void* d_out, int out_size) {
    (void)in_sizes; (void)n_in; (void)out_size;
    const float* in = (const float*)d_in[0];
    float* out = (float*)d_out;

    dim3 block(32, 8, 1);
    dim3 grid(IMG_W / TILE_W, IMG_H / OUT_H, NIMG);
    median5x5_h2_kernel<<<grid, block>>>(in, out);
}

// round 13
// speedup vs baseline: 1.3292x; 1.0612x over previous
#include <cuda_runtime.h>
#include <cuda_fp16.h>

// MedianBlur 5x5, fp32 I/O, 12 images of 1024x1024, zero padding (same).
// Round-13: round-10 champion + tiling/loader trims. OUT_H=32 (4 groups,
// exact divisor -> no y guard; waves 4.65->3.46, halo 1.167->1.125),
// interior-x fast-path loader (no per-iteration bounds branch for 30/32
// x-blocks). Network = rounds 9/10 (11-candidate pruned selection),
// wide-LDS packed tile -> rel_err bit-identical.

#define IMG_H 1024
#define IMG_W 1024
#define NIMG  12

#define TILE_W 128            // output cols per block (32 threads * 4 px)
#define OUT_H  32             // output rows per block (4 groups of 8)
#define SMEM_H 36             // OUT_H + 4 halo
#define KCOLS 34              // packed cols per group: c = 4*k + g, c in [0,136)

typedef __half2 h2;

__device__ __forceinline__ h2 mn2(h2 a, h2 b) { return __hmin2(a, b); }
__device__ __forceinline__ h2 mx2(h2 a, h2 b) { return __hmax2(a, b); }

__device__ __forceinline__ void ce(h2& a, h2& b) {
    h2 t = mn2(a, b);
    b = mx2(a, b);
    a = t;
}

// 9-CE optimal sorting network for 5 elements (ascending), element-wise on half2.
__device__ __forceinline__ void sort5(h2& v0, h2& v1, h2& v2, h2& v3, h2& v4) {
    ce(v0, v1); ce(v3, v4); ce(v2, v4); ce(v2, v3); ce(v0, v3);
    ce(v0, v2); ce(v1, v4); ce(v1, v3); ce(v1, v2);
}

// Constrained merge of top chains, DROPPING rank 0 (provably non-median). 5 ops.
__device__ __forceinline__ void merge_top4(h2 x0, h2 x1, h2 y0, h2 y1, h2 y2,
                                           h2& a1, h2& a2, h2& a3, h2& a4) {
    h2 p = mx2(x0, y0);
    h2 q = mn2(x1, y1);
    a3 = mx2(x1, y1);
    a1 = mn2(p, q);
    a2 = mx2(p, q);
    a4 = y2;
}

// Constrained merge of bottom chains, DROPPING rank 4 (provably non-median). 5 ops.
__device__ __forceinline__ void merge_bot4(h2 x0, h2 x1, h2 y0, h2 y1, h2 y2,
                                           h2& b0, h2& b1, h2& b2, h2& b3) {
    b0 = y0;
    b1 = mn2(x0, y1);
    h2 p = mx2(x0, y1);
    h2 q = mn2(x1, y2);
    b2 = mn2(p, q);
    b3 = mx2(p, q);
}

// Batcher odd-even merge of two sorted 4-chains, ONLY ranks 2..5 of 8. 14 ops.
__device__ __forceinline__ void merge44_mid4(h2 a1, h2 a2, h2 a3, h2 a4,
                                             h2 b0, h2 b1, h2 b2, h2 b3,
                                             h2& s0, h2& s1, h2& s2, h2& s3) {
    h2 t  = mx2(a1, b0);
    h2 u  = mn2(a3, b2);
    h2 E3 = mx2(a3, b2);
    h2 E1 = mn2(t, u);
    h2 E2 = mx2(t, u);
    h2 O0 = mn2(a2, b1);
    h2 t2 = mx2(a2, b1);
    h2 u2 = mn2(a4, b3);
    h2 O1 = mn2(t2, u2);
    h2 O2 = mx2(t2, u2);
    s0 = mx2(O0, E1);
    s1 = mn2(O1, E2);
    s2 = mx2(O1, E2);
    s3 = mn2(O2, E3);
}

// Finisher: med11 == med7({s0<=s1<=s2<=s3} U {m0<=m1<=m2}). 10 ops.
__device__ __forceinline__ h2 med7_fin(h2 s0, h2 s1, h2 s2, h2 s3,
                                       h2 m0, h2 m1, h2 m2) {
    h2 u0 = mx2(s0, m0);
    h2 u3 = mn2(s3, m2);
    h2 p = mn2(u3, m1);
    h2 q = mx2(u3, m1);
    h2 a = mx2(s1, p);
    h2 b = mn2(s2, q);
    h2 lo = mn2(a, b);
    h2 hi = mx2(a, b);
    return mx2(lo, mn2(hi, u0));
}

__global__ __launch_bounds__(256, 6)
void median5x5_h2_kernel(const float* __restrict__ in, float* __restrict__ out) {
    // Packed tile: P2[c] = (h[c], h[c+2]), c = 4k + g, stored p2t[r][k][g]
    // with g contiguous -> 16-byte groups readable by LDS.128 / LDS.64.
    __shared__ __align__(16) h2 p2t[SMEM_H][KCOLS][4];

    const int n   = blockIdx.z;
    const int x0b = blockIdx.x * TILE_W;
    const int y0b = blockIdx.y * OUT_H;
    const float* img = in + (size_t)n * IMG_H * IMG_W;

    const int tx = threadIdx.x;
    const int ty = threadIdx.y;
    const int tid = ty * 32 + tx;

    // Interior in x: every k has gx0 >= 0 and gx0+5 <= 1023.
    const bool xin = (x0b >= 4) && (x0b + 133 <= IMG_W - 1);

    // Loader: 36 x 34 packed-column tasks, zero padding on edges.
    if (xin) {
        for (int i = tid; i < SMEM_H * KCOLS; i += 256) {
            const int r  = i / KCOLS;
            const int k  = i - r * KCOLS;
            const int gy  = y0b + r - 2;
            float f0 = 0.f, f1 = 0.f, f2 = 0.f, f3 = 0.f, f4 = 0.f, f5 = 0.f;
            if ((unsigned)gy < IMG_H) {
                const float* rowp = img + (size_t)gy * IMG_W + (x0b - 4 + k * 4);
                const float4 fa = *reinterpret_cast<const float4*>(rowp);
                const float2 fb = *reinterpret_cast<const float2*>(rowp + 4);
                f0 = fa.x; f1 = fa.y; f2 = fa.z; f3 = fa.w; f4 = fb.x; f5 = fb.y;
            }
            const h2 p0 = __float22half2_rn(make_float2(f0, f2));
            const h2 p1 = __float22half2_rn(make_float2(f1, f3));
            const h2 p2 = __float22half2_rn(make_float2(f2, f4));
            const h2 p3 = __float22half2_rn(make_float2(f3, f5));
            uint4 w;
            w.x = *reinterpret_cast<const unsigned*>(&p0);
            w.y = *reinterpret_cast<const unsigned*>(&p1);
            w.z = *reinterpret_cast<const unsigned*>(&p2);
            w.w = *reinterpret_cast<const unsigned*>(&p3);
            *reinterpret_cast<uint4*>(&p2t[r][k][0]) = w;
        }
    } else {
        for (int i = tid; i < SMEM_H * KCOLS; i += 256) {
            const int r  = i / KCOLS;
            const int k  = i - r * KCOLS;
            const int gy  = y0b + r - 2;
            const int gx0 = x0b - 4 + k * 4;
            float f0 = 0.f, f1 = 0.f, f2 = 0.f, f3 = 0.f, f4 = 0.f, f5 = 0.f;
            if ((unsigned)gy < IMG_H) {
                const float* rowp = img + (size_t)gy * IMG_W;
                if (gx0 >= 0 && gx0 + 5 < IMG_W) {
                    const float4 fa = *reinterpret_cast<const float4*>(rowp + gx0);
                    const float2 fb = *reinterpret_cast<const float2*>(rowp + gx0 + 4);
                    f0 = fa.x; f1 = fa.y; f2 = fa.z; f3 = fa.w; f4 = fb.x; f5 = fb.y;
                } else {
                    if ((unsigned)gx0       < IMG_W) f0 = rowp[gx0];
                    if ((unsigned)(gx0 + 1) < IMG_W) f1 = rowp[gx0 + 1];
                    if ((unsigned)(gx0 + 2) < IMG_W) f2 = rowp[gx0 + 2];
                    if ((unsigned)(gx0 + 3) < IMG_W) f3 = rowp[gx0 + 3];
                    if ((unsigned)(gx0 + 4) < IMG_W) f4 = rowp[gx0 + 4];
                    if ((unsigned)(gx0 + 5) < IMG_W) f5 = rowp[gx0 + 5];
                }
            }
            const h2 p0 = __float22half2_rn(make_float2(f0, f2));
            const h2 p1 = __float22half2_rn(make_float2(f1, f3));
            const h2 p2 = __float22half2_rn(make_float2(f2, f4));
            const h2 p3 = __float22half2_rn(make_float2(f3, f5));
            uint4 w;
            w.x = *reinterpret_cast<const unsigned*>(&p0);
            w.y = *reinterpret_cast<const unsigned*>(&p1);
            w.z = *reinterpret_cast<const unsigned*>(&p2);
            w.w = *reinterpret_cast<const unsigned*>(&p3);
            *reinterpret_cast<uint4*>(&p2t[r][k][0]) = w;
        }
    }
    __syncthreads();

    // Four output row-groups per thread; col[6][5] registers reused.
    #pragma unroll 1
    for (int gr = 0; gr < 4; gr++) {
        const int rb = ty + gr * 8;          // smem base row of the window
        const int y  = y0b + rb;             // global output row (always < IMG_H)

        // Packed col m (m=0..5) is P2[4tx+2+m]:
        //   m=0,1 -> p2t[row][tx][2..3]   (one LDS.64)
        //   m=2..5 -> p2t[row][tx+1][0..3] (one LDS.128)
        h2 col[6][5];
        #pragma unroll
        for (int i = 0; i < 5; i++) {
            const uint2 lo = *reinterpret_cast<const uint2*>(&p2t[rb + i][tx][2]);
            const uint4 hi = *reinterpret_cast<const uint4*>(&p2t[rb + i][tx + 1][0]);
            col[0][i] = *reinterpret_cast<const h2*>(&lo.x);
            col[1][i] = *reinterpret_cast<const h2*>(&lo.y);
            col[2][i] = *reinterpret_cast<const h2*>(&hi.x);
            col[3][i] = *reinterpret_cast<const h2*>(&hi.y);
            col[4][i] = *reinterpret_cast<const h2*>(&hi.z);
            col[5][i] = *reinterpret_cast<const h2*>(&hi.w);
        }

        #pragma unroll
        for (int m = 0; m < 6; m++)
            sort5(col[m][0], col[m][1], col[m][2], col[m][3], col[m][4]);

        // ---- Row phase: partial shared sorts of cols 1..4, rank-insert c0/c5 ----
        h2 a03, a04, a12, a13, a14, aM1, aM2, aM3, a30, a31, a32, a40, a41;
        h2 b03, b04, b12, b13, b14, bM1, bM2, bM3, b30, b31, b32, b40, b41;

        {   // row 0: top2 of 4, insert -> ranks {3,4}
            h2 a = mn2(col[1][0], col[2][0]), b = mx2(col[1][0], col[2][0]);
            h2 c = mn2(col[3][0], col[4][0]), d = mx2(col[3][0], col[4][0]);
            h2 q3 = mx2(b, d);
            h2 q2 = mx2(mn2(b, d), mx2(a, c));
            h2 xa = col[0][0], xb = col[5][0];
            a04 = mx2(q3, xa); a03 = mx2(q2, mn2(q3, xa));
            b04 = mx2(q3, xb); b03 = mx2(q2, mn2(q3, xb));
        }
        {   // row 1: sort4 minus q0, insert -> ranks {2,3,4}
            h2 v0 = col[1][1], v1 = col[2][1], v2 = col[3][1], v3 = col[4][1];
            ce(v0, v1); ce(v2, v3);
            v2 = mx2(v0, v2);
            ce(v1, v3); ce(v1, v2);
            const h2 q1 = v1, q2 = v2, q3 = v3;
            h2 xa = col[0][1], xb = col[5][1];
            a14 = mx2(q3, xa); a13 = mx2(q2, mn2(q3, xa)); a12 = mx2(q1, mn2(q2, xa));
            b14 = mx2(q3, xb); b13 = mx2(q2, mn2(q3, xb)); b12 = mx2(q1, mn2(q2, xb));
        }
        {   // row 2: full sort4, insert -> mid3 ranks {1,2,3}
            h2 q0 = col[1][2], q1 = col[2][2], q2 = col[3][2], q3 = col[4][2];
            ce(q0, q1); ce(q2, q3); ce(q0, q2); ce(q1, q3); ce(q1, q2);
            h2 xa = col[0][2], xb = col[5][2];
            aM3 = mx2(q2, mn2(q3, xa)); aM2 = mx2(q1, mn2(q2, xa)); aM1 = mx2(q0, mn2(q1, xa));
            bM3 = mx2(q2, mn2(q3, xb)); bM2 = mx2(q1, mn2(q2, xb)); bM1 = mx2(q0, mn2(q1, xb));
        }
        {   // row 3: sort4 minus q3, insert -> ranks {0,1,2}
            h2 v0 = col[1][3], v1 = col[2][3], v2 = col[3][3], v3 = col[4][3];
            ce(v0, v1); ce(v2, v3); ce(v0, v2);
            v1 = mn2(v1, v3);
            ce(v1, v2);
            const h2 q0 = v0, q1 = v1, q2 = v2;
            h2 xa = col[0][3], xb = col[5][3];
            a30 = mn2(q0, xa); a31 = mx2(q0, mn2(q1, xa)); a32 = mx2(q1, mn2(q2, xa));
            b30 = mn2(q0, xb); b31 = mx2(q0, mn2(q1, xb)); b32 = mx2(q1, mn2(q2, xb));
        }
        {   // row 4: bottom2 of 4, insert -> ranks {0,1}
            h2 a = mn2(col[1][4], col[2][4]), b = mx2(col[1][4], col[2][4]);
            h2 c = mn2(col[3][4], col[4][4]), d = mx2(col[3][4], col[4][4]);
            h2 q0 = mn2(a, c);
            h2 q1 = mn2(mx2(a, c), mn2(b, d));
            h2 xa = col[0][4], xb = col[5][4];
            a40 = mn2(q0, xa); a41 = mx2(q0, mn2(q1, xa));
            b40 = mn2(q0, xb); b41 = mx2(q0, mn2(q1, xb));
        }

        // ---- Merge phase per network (pruned 11-candidate selection) ----
        h2 rA, rB;
        {
            h2 a1, a2, a3, a4, c0, c1, c2, c3;
            merge_top4(a03, a04, a12, a13, a14, a1, a2, a3, a4);
            merge_bot4(a40, a41, a30, a31, a32, c0, c1, c2, c3);
            h2 s0, s1, s2, s3;
            merge44_mid4(a1, a2, a3, a4, c0, c1, c2, c3, s0, s1, s2, s3);
            rA = med7_fin(s0, s1, s2, s3, aM1, aM2, aM3);
        }
        {
            h2 a1, a2, a3, a4, c0, c1, c2, c3;
            merge_top4(b03, b04, b12, b13, b14, a1, a2, a3, a4);
            merge_bot4(b40, b41, b30, b31, b32, c0, c1, c2, c3);
            h2 s0, s1, s2, s3;
            merge44_mid4(a1, a2, a3, a4, c0, c1, c2, c3, s0, s1, s2, s3);
            rB = med7_fin(s0, s1, s2, s3, bM1, bM2, bM3);
        }

        float4 res;
        res.x = __low2float(rA);    // pixel p0
        res.y = __low2float(rB);    // pixel p0+1
        res.z = __high2float(rA);   // pixel p0+2
        res.w = __high2float(rB);   // pixel p0+3

        float* orow = out + (size_t)n * IMG_H * IMG_W
                          + (size_t)y * IMG_W + x0b + tx * 4;
        *reinterpret_cast<float4*>(orow) = res;
    }
}

extern "C" void kernel_launch(void* const* d_in, const int* in_sizes, int n_in,
                              void* d_out, int out_size) {
    (void)in_sizes; (void)n_in; (void)out_size;
    const float* in = (const float*)d_in[0];
    float* out = (float*)d_out;

    dim3 block(32, 8, 1);
    dim3 grid(IMG_W / TILE_W, IMG_H / OUT_H, NIMG);
    median5x5_h2_kernel<<<grid, block>>>(in, out);
}

// round 14
// speedup vs baseline: 1.5381x; 1.1571x over previous
#include <cuda_runtime.h>
#include <cuda_fp16.h>

// MedianBlur 5x5, fp32 I/O, 12 images of 1024x1024, zero padding (same).
// Round-14: 8 px/thread. Distance-4 half2 packing P4[c]=(h[c],h[c+4]);
// 8 sorted packed columns serve 4 networks (A:cols0-4, B:1-5, C:2-6, D:3-7)
// -> column-sort cost 18/px instead of 27/px. Row+merge phases = round 13
// (shared sort4 + rank-insert, 11-candidate pruned selection) applied twice
// on col slices [0..5] and [2..7]. rel_err bit-identical.

#define IMG_H 1024
#define IMG_W 1024
#define NIMG  12

#define TILE_W 256            // output cols per block (32 threads * 8 px)
#define OUT_H  24             // output rows per block (3 groups of 8)
#define SMEM_H 28             // OUT_H + 4 halo
#define K8     33             // packed-col groups: c = 8k+g, c in [0,264)

typedef __half2 h2;

__device__ __forceinline__ h2 mn2(h2 a, h2 b) { return __hmin2(a, b); }
__device__ __forceinline__ h2 mx2(h2 a, h2 b) { return __hmax2(a, b); }

__device__ __forceinline__ void ce(h2& a, h2& b) {
    h2 t = mn2(a, b);
    b = mx2(a, b);
    a = t;
}

// 9-CE optimal sorting network for 5 elements (ascending), element-wise on half2.
__device__ __forceinline__ void sort5(h2& v0, h2& v1, h2& v2, h2& v3, h2& v4) {
    ce(v0, v1); ce(v3, v4); ce(v2, v4); ce(v2, v3); ce(v0, v3);
    ce(v0, v2); ce(v1, v4); ce(v1, v3); ce(v1, v2);
}

// Constrained merge of top chains, DROPPING rank 0 (provably non-median). 5 ops.
__device__ __forceinline__ void merge_top4(h2 x0, h2 x1, h2 y0, h2 y1, h2 y2,
                                           h2& a1, h2& a2, h2& a3, h2& a4) {
    h2 p = mx2(x0, y0);
    h2 q = mn2(x1, y1);
    a3 = mx2(x1, y1);
    a1 = mn2(p, q);
    a2 = mx2(p, q);
    a4 = y2;
}

// Constrained merge of bottom chains, DROPPING rank 4 (provably non-median). 5 ops.
__device__ __forceinline__ void merge_bot4(h2 x0, h2 x1, h2 y0, h2 y1, h2 y2,
                                           h2& b0, h2& b1, h2& b2, h2& b3) {
    b0 = y0;
    b1 = mn2(x0, y1);
    h2 p = mx2(x0, y1);
    h2 q = mn2(x1, y2);
    b2 = mn2(p, q);
    b3 = mx2(p, q);
}

// Batcher odd-even merge of two sorted 4-chains, ONLY ranks 2..5 of 8. 14 ops.
__device__ __forceinline__ void merge44_mid4(h2 a1, h2 a2, h2 a3, h2 a4,
                                             h2 b0, h2 b1, h2 b2, h2 b3,
                                             h2& s0, h2& s1, h2& s2, h2& s3) {
    h2 t  = mx2(a1, b0);
    h2 u  = mn2(a3, b2);
    h2 E3 = mx2(a3, b2);
    h2 E1 = mn2(t, u);
    h2 E2 = mx2(t, u);
    h2 O0 = mn2(a2, b1);
    h2 t2 = mx2(a2, b1);
    h2 u2 = mn2(a4, b3);
    h2 O1 = mn2(t2, u2);
    h2 O2 = mx2(t2, u2);
    s0 = mx2(O0, E1);
    s1 = mn2(O1, E2);
    s2 = mx2(O1, E2);
    s3 = mn2(O2, E3);
}

// Finisher: med11 == med7({s0<=s1<=s2<=s3} U {m0<=m1<=m2}). 10 ops.
__device__ __forceinline__ h2 med7_fin(h2 s0, h2 s1, h2 s2, h2 s3,
                                       h2 m0, h2 m1, h2 m2) {
    h2 u0 = mx2(s0, m0);
    h2 u3 = mn2(s3, m2);
    h2 p = mn2(u3, m1);
    h2 q = mx2(u3, m1);
    h2 a = mx2(s1, p);
    h2 b = mn2(s2, q);
    h2 lo = mn2(a, b);
    h2 hi = mx2(a, b);
    return mx2(lo, mn2(hi, u0));
}

// Two medians from 6 sorted columns cs[0..5] (networks on cs[0..4], cs[1..5]).
// Row phase: shared sort4 of cs[1..4] per row + rank-insert cs[0] / cs[5];
// merge phase: pruned 11-candidate selection. (= round-13 network.)
__device__ __forceinline__ void med_pair(const h2 cs[6][5], h2& rA, h2& rB) {
    h2 a03, a04, a12, a13, a14, aM1, aM2, aM3, a30, a31, a32, a40, a41;
    h2 b03, b04, b12, b13, b14, bM1, bM2, bM3, b30, b31, b32, b40, b41;

    {   // row 0: top2 of 4, insert -> ranks {3,4}
        h2 a = mn2(cs[1][0], cs[2][0]), b = mx2(cs[1][0], cs[2][0]);
        h2 c = mn2(cs[3][0], cs[4][0]), d = mx2(cs[3][0], cs[4][0]);
        h2 q3 = mx2(b, d);
        h2 q2 = mx2(mn2(b, d), mx2(a, c));
        h2 xa = cs[0][0], xb = cs[5][0];
        a04 = mx2(q3, xa); a03 = mx2(q2, mn2(q3, xa));
        b04 = mx2(q3, xb); b03 = mx2(q2, mn2(q3, xb));
    }
    {   // row 1: sort4 minus q0, insert -> ranks {2,3,4}
        h2 v0 = cs[1][1], v1 = cs[2][1], v2 = cs[3][1], v3 = cs[4][1];
        ce(v0, v1); ce(v2, v3);
        v2 = mx2(v0, v2);
        ce(v1, v3); ce(v1, v2);
        const h2 q1 = v1, q2 = v2, q3 = v3;
        h2 xa = cs[0][1], xb = cs[5][1];
        a14 = mx2(q3, xa); a13 = mx2(q2, mn2(q3, xa)); a12 = mx2(q1, mn2(q2, xa));
        b14 = mx2(q3, xb); b13 = mx2(q2, mn2(q3, xb)); b12 = mx2(q1, mn2(q2, xb));
    }
    {   // row 2: full sort4, insert -> mid3 ranks {1,2,3}
        h2 q0 = cs[1][2], q1 = cs[2][2], q2 = cs[3][2], q3 = cs[4][2];
        ce(q0, q1); ce(q2, q3); ce(q0, q2); ce(q1, q3); ce(q1, q2);
        h2 xa = cs[0][2], xb = cs[5][2];
        aM3 = mx2(q2, mn2(q3, xa)); aM2 = mx2(q1, mn2(q2, xa)); aM1 = mx2(q0, mn2(q1, xa));
        bM3 = mx2(q2, mn2(q3, xb)); bM2 = mx2(q1, mn2(q2, xb)); bM1 = mx2(q0, mn2(q1, xb));
    }
    {   // row 3: sort4 minus q3, insert -> ranks {0,1,2}
        h2 v0 = cs[1][3], v1 = cs[2][3], v2 = cs[3][3], v3 = cs[4][3];
        ce(v0, v1); ce(v2, v3); ce(v0, v2);
        v1 = mn2(v1, v3);
        ce(v1, v2);
        const h2 q0 = v0, q1 = v1, q2 = v2;
        h2 xa = cs[0][3], xb = cs[5][3];
        a30 = mn2(q0, xa); a31 = mx2(q0, mn2(q1, xa)); a32 = mx2(q1, mn2(q2, xa));
        b30 = mn2(q0, xb); b31 = mx2(q0, mn2(q1, xb)); b32 = mx2(q1, mn2(q2, xb));
    }
    {   // row 4: bottom2 of 4, insert -> ranks {0,1}
        h2 a = mn2(cs[1][4], cs[2][4]), b = mx2(cs[1][4], cs[2][4]);
        h2 c = mn2(cs[3][4], cs[4][4]), d = mx2(cs[3][4], cs[4][4]);
        h2 q0 = mn2(a, c);
        h2 q1 = mn2(mx2(a, c), mn2(b, d));
        h2 xa = cs[0][4], xb = cs[5][4];
        a40 = mn2(q0, xa); a41 = mx2(q0, mn2(q1, xa));
        b40 = mn2(q0, xb); b41 = mx2(q0, mn2(q1, xb));
    }
    {
        h2 a1, a2, a3, a4, c0, c1, c2, c3;
        merge_top4(a03, a04, a12, a13, a14, a1, a2, a3, a4);
        merge_bot4(a40, a41, a30, a31, a32, c0, c1, c2, c3);
        h2 s0, s1, s2, s3;
        merge44_mid4(a1, a2, a3, a4, c0, c1, c2, c3, s0, s1, s2, s3);
        rA = med7_fin(s0, s1, s2, s3, aM1, aM2, aM3);
    }
    {
        h2 a1, a2, a3, a4, c0, c1, c2, c3;
        merge_top4(b03, b04, b12, b13, b14, a1, a2, a3, a4);
        merge_bot4(b40, b41, b30, b31, b32, c0, c1, c2, c3);
        h2 s0, s1, s2, s3;
        merge44_mid4(a1, a2, a3, a4, c0, c1, c2, c3, s0, s1, s2, s3);
        rB = med7_fin(s0, s1, s2, s3, bM1, bM2, bM3);
    }
}

__global__ __launch_bounds__(256, 5)
void median5x5_h2_kernel(const float* __restrict__ in, float* __restrict__ out) {
    // Packed tile: P4[c] = (h[c], h[c+4]), c = 8k + g, stored pt[r][k][g],
    // g contiguous (32B/group) -> wide LDS. h-col c <-> gx = x0b - 4 + c.
    __shared__ __align__(16) h2 pt[SMEM_H][K8][8];

    const int n   = blockIdx.z;
    const int x0b = blockIdx.x * TILE_W;
    const int y0b = blockIdx.y * OUT_H;
    const float* img = in + (size_t)n * IMG_H * IMG_W;

    const int tx = threadIdx.x;
    const int ty = threadIdx.y;
    const int tid = ty * 32 + tx;

    // Interior in x: every task reads gx in [x0b-4, x0b+267], all in-range.
    const bool xin = (x0b >= 4) && (x0b + 267 <= IMG_W - 1);

    if (xin) {
        for (int i = tid; i < SMEM_H * K8; i += 256) {
            const int r = i / K8;
            const int k = i - r * K8;
            const int gy = y0b + r - 2;
            float f[12];
            #pragma unroll
            for (int j = 0; j < 12; j++) f[j] = 0.f;
            if ((unsigned)gy < IMG_H) {
                const float* rowp = img + (size_t)gy * IMG_W + (x0b - 4 + k * 8);
                const float4 fa = *reinterpret_cast<const float4*>(rowp);
                const float4 fb = *reinterpret_cast<const float4*>(rowp + 4);
                const float4 fc = *reinterpret_cast<const float4*>(rowp + 8);
                f[0]=fa.x; f[1]=fa.y; f[2]=fa.z; f[3]=fa.w;
                f[4]=fb.x; f[5]=fb.y; f[6]=fb.z; f[7]=fb.w;
                f[8]=fc.x; f[9]=fc.y; f[10]=fc.z; f[11]=fc.w;
            }
            unsigned wv[8];
            #pragma unroll
            for (int g = 0; g < 8; g++) {
                const h2 p = __float22half2_rn(make_float2(f[g], f[g + 4]));
                wv[g] = *reinterpret_cast<const unsigned*>(&p);
            }
            uint4 w0 = make_uint4(wv[0], wv[1], wv[2], wv[3]);
            uint4 w1 = make_uint4(wv[4], wv[5], wv[6], wv[7]);
            *reinterpret_cast<uint4*>(&pt[r][k][0]) = w0;
            *reinterpret_cast<uint4*>(&pt[r][k][4]) = w1;
        }
    } else {
        for (int i = tid; i < SMEM_H * K8; i += 256) {
            const int r = i / K8;
            const int k = i - r * K8;
            const int gy = y0b + r - 2;
            const int gx0 = x0b - 4 + k * 8;
            float f[12];
            #pragma unroll
            for (int j = 0; j < 12; j++) f[j] = 0.f;
            if ((unsigned)gy < IMG_H) {
                const float* rowp = img + (size_t)gy * IMG_W;
                if (gx0 >= 0 && gx0 + 11 < IMG_W) {
                    const float4 fa = *reinterpret_cast<const float4*>(rowp + gx0);
                    const float4 fb = *reinterpret_cast<const float4*>(rowp + gx0 + 4);
                    const float4 fc = *reinterpret_cast<const float4*>(rowp + gx0 + 8);
                    f[0]=fa.x; f[1]=fa.y; f[2]=fa.z; f[3]=fa.w;
                    f[4]=fb.x; f[5]=fb.y; f[6]=fb.z; f[7]=fb.w;
                    f[8]=fc.x; f[9]=fc.y; f[10]=fc.z; f[11]=fc.w;
                } else {
                    #pragma unroll
                    for (int j = 0; j < 12; j++)
                        if ((unsigned)(gx0 + j) < IMG_W) f[j] = rowp[gx0 + j];
                }
            }
            unsigned wv[8];
            #pragma unroll
            for (int g = 0; g < 8; g++) {
                const h2 p = __float22half2_rn(make_float2(f[g], f[g + 4]));
                wv[g] = *reinterpret_cast<const unsigned*>(&p);
            }
            uint4 w0 = make_uint4(wv[0], wv[1], wv[2], wv[3]);
            uint4 w1 = make_uint4(wv[4], wv[5], wv[6], wv[7]);
            *reinterpret_cast<uint4*>(&pt[r][k][0]) = w0;
            *reinterpret_cast<uint4*>(&pt[r][k][4]) = w1;
        }
    }
    __syncthreads();

    // Thread handles pixels p0..p0+7 (p0 = tx*8) as 4 distance-4 pairs.
    // Network column m (m=0..7) is P4[8tx + 2 + m]:
    //   m=0,1  -> pt[row][tx][2..3]     (LDS.64)
    //   m=2..5 -> pt[row][tx][4..7]     (LDS.128)
    //   m=6,7  -> pt[row][tx+1][0..1]   (LDS.64)
    #pragma unroll 1
    for (int gr = 0; gr < 3; gr++) {
        const int rb = ty + gr * 8;          // smem base row of the window
        const int y  = y0b + rb;             // global output row
        if (y >= IMG_H) break;

        h2 col[8][5];
        #pragma unroll
        for (int i = 0; i < 5; i++) {
            const uint2 a = *reinterpret_cast<const uint2*>(&pt[rb + i][tx][2]);
            const uint4 b = *reinterpret_cast<const uint4*>(&pt[rb + i][tx][4]);
            const uint2 c = *reinterpret_cast<const uint2*>(&pt[rb + i][tx + 1][0]);
            col[0][i] = *reinterpret_cast<const h2*>(&a.x);
            col[1][i] = *reinterpret_cast<const h2*>(&a.y);
            col[2][i] = *reinterpret_cast<const h2*>(&b.x);
            col[3][i] = *reinterpret_cast<const h2*>(&b.y);
            col[4][i] = *reinterpret_cast<const h2*>(&b.z);
            col[5][i] = *reinterpret_cast<const h2*>(&b.w);
            col[6][i] = *reinterpret_cast<const h2*>(&c.x);
            col[7][i] = *reinterpret_cast<const h2*>(&c.y);
        }

        #pragma unroll
        for (int m = 0; m < 8; m++)
            sort5(col[m][0], col[m][1], col[m][2], col[m][3], col[m][4]);

        h2 rA, rB, rC, rD;
        med_pair(&col[0], rA, rB);   // pixels (p0, p0+4), (p0+1, p0+5)
        med_pair(&col[2], rC, rD);   // pixels (p0+2, p0+6), (p0+3, p0+7)

        float4 o0, o1;
        o0.x = __low2float(rA);  o0.y = __low2float(rB);
        o0.z = __low2float(rC);  o0.w = __low2float(rD);
        o1.x = __high2float(rA); o1.y = __high2float(rB);
        o1.z = __high2float(rC); o1.w = __high2float(rD);

        float* orow = out + (size_t)n * IMG_H * IMG_W
                          + (size_t)y * IMG_W + x0b + tx * 8;
        *reinterpret_cast<float4*>(orow)     = o0;
        *reinterpret_cast<float4*>(orow + 4) = o1;
    }
}

extern "C" void kernel_launch(void* const* d_in, const int* in_sizes, int n_in,
                              void* d_out, int out_size) {
    (void)in_sizes; (void)n_in; (void)out_size;
    const float* in = (const float*)d_in[0];
    float* out = (float*)d_out;

    dim3 block(32, 8, 1);
    dim3 grid(IMG_W / TILE_W, (IMG_H + OUT_H - 1) / OUT_H, NIMG);
    median5x5_h2_kernel<<<grid, block>>>(in, out);
}